// round 12
// baseline (speedup 1.0000x reference)
#include <cuda_runtime.h>
#include <cuda_bf16.h>

typedef unsigned long long u64;

// ---------------- packed f32x2 helpers ----------------
__device__ __forceinline__ u64 pack2(float x) {
    u64 r; unsigned u = __float_as_uint(x);
    asm("mov.b64 %0, {%1, %2};" : "=l"(r) : "r"(u), "r"(u));
    return r;
}
__device__ __forceinline__ void fma2(u64 &acc, u64 a, u64 b) {
    asm("fma.rn.f32x2 %0, %1, %2, %0;" : "+l"(acc) : "l"(a), "l"(b));
}
__device__ __forceinline__ float2 unpack2(u64 v) {
    unsigned lo, hi;
    asm("mov.b64 {%0, %1}, %2;" : "=r"(lo), "=r"(hi) : "l"(v));
    return make_float2(__uint_as_float(lo), __uint_as_float(hi));
}

// ---------------- cp.async helpers ----------------
__device__ __forceinline__ unsigned smem_u32(const void* p) {
    return (unsigned)__cvta_generic_to_shared(p);
}
__device__ __forceinline__ void cp4(unsigned dst, const float* src, int srcsize) {
    asm volatile("cp.async.ca.shared.global [%0], [%1], 4, %2;"
                 :: "r"(dst), "l"(src), "r"(srcsize));
}
__device__ __forceinline__ void cp4u(unsigned dst, const float* src) {
    asm volatile("cp.async.ca.shared.global [%0], [%1], 4;"
                 :: "r"(dst), "l"(src));
}
__device__ __forceinline__ void cp16(unsigned dst, const void* src) {
    asm volatile("cp.async.cg.shared.global [%0], [%1], 16;"
                 :: "r"(dst), "l"(src));
}
__device__ __forceinline__ void cp_commit() {
    asm volatile("cp.async.commit_group;");
}
template<int N>
__device__ __forceinline__ void cp_wait() {
    asm volatile("cp.async.wait_group %0;" :: "n"(N));
}

// ---------------- mma.sync helpers (baseline PTX, no 'a' features) ----------------
__device__ __forceinline__ void ldm4(unsigned r[4], unsigned addr) {
    asm volatile("ldmatrix.sync.aligned.m8n8.x4.shared.b16 {%0,%1,%2,%3}, [%4];"
                 : "=r"(r[0]), "=r"(r[1]), "=r"(r[2]), "=r"(r[3]) : "r"(addr));
}
__device__ __forceinline__ void mma16816(float c[4], const unsigned a[4],
                                         unsigned b0, unsigned b1) {
    asm volatile("mma.sync.aligned.m16n8k16.row.col.f32.bf16.bf16.f32 "
                 "{%0,%1,%2,%3}, {%4,%5,%6,%7}, {%8,%9}, {%0,%1,%2,%3};"
                 : "+f"(c[0]), "+f"(c[1]), "+f"(c[2]), "+f"(c[3])
                 : "r"(a[0]), "r"(a[1]), "r"(a[2]), "r"(a[3]), "r"(b0), "r"(b1));
}
__device__ __forceinline__ void bar_half(int id) {
    asm volatile("bar.sync %0, %1;" :: "r"(id), "r"(128) : "memory");
}

// ---------------- problem constants ----------------
#define NB    32
#define OH1   56
#define NPIX1 (OH1*OH1)   // 3136
#define N1    (NB*NPIX1)  // 100352
#define K1    243
#define K1PAD 248
#define OH2   24
#define P2    (OH2*OH2)   // 576
#define N2    (NB*P2)     // 18432
#define K2    20736
#define MCH   256
#define RR    32
#define DD    8
#define CC    10
#define OO    16

// conv2 mma tiling: per half-CTA pipeline (128 threads, 4 warps)
#define KCH    32
#define NCH    (K2/KCH)     // 648
// per-half stage: A_hi[128x64B] | A_lo | B_hi[64x80B] | B_lo
#define A_LO_OFF  8192
#define B_HI_OFF  16384
#define B_LO_OFF  21504
#define STAGE_SZ  26624
#define HALF_SZ   (2*STAGE_SZ)        // 53248
#define CONV2_SMEM (2*HALF_SZ)        // 106496

// ---------------- scratch (static device memory only) ----------------
__device__ __align__(16) unsigned g_h1p[NB*MCH*NPIX1];   // conv1 out packed (bf16hi | bf16lo<<16)
__device__ __align__(16) float    g_caps[NB*RR*P2*DD];
__device__ __align__(16) float    g_w1t[K1PAD*MCH];
__device__ __align__(16) unsigned g_w2img[NCH*2*256*16]; // [chunk][plane][ch][16 u32 = 32 bf16]
__device__ __align__(16) float    g_WV[NB*RR*CC*DD];
__device__ __align__(16) float    g_G[NB*RR*CC*DD];
__device__ __align__(16) float    g_v[NB*CC*OO];
__device__ __align__(16) float    g_blog[NB*RR*P2*CC];

// ---------------- bf16 split pack ----------------
__device__ __forceinline__ unsigned pack_split(float v) {
    __nv_bfloat16 h = __float2bfloat16(v);
    float hf = __bfloat162float(h);
    __nv_bfloat16 l = __float2bfloat16(v - hf);
    return (unsigned)__bfloat16_as_ushort(h) | ((unsigned)__bfloat16_as_ushort(l) << 16);
}

// ---------------- conv1 weight transpose ----------------
__global__ void wt1_kernel(const float* __restrict__ w) {
    int idx = blockIdx.x * 256 + threadIdx.x;
    if (idx >= K1PAD*MCH) return;
    int k = idx >> 8, m = idx & 255;
    float v = 0.f;
    if (k < K1) v = w[m*K1 + k];
    g_w1t[idx] = v;
}

// ---------------- conv2 weight split into linear image ----------------
__global__ void wsplit_kernel(const float* __restrict__ w2) {
    int t  = blockIdx.x * 256 + threadIdx.x;  // 256ch * K2/2 pairs
    int ch = t / (K2/2);
    int kp = t - ch*(K2/2);
    int k  = 2*kp;
    unsigned p0 = pack_split(w2[ch*K2 + k]);
    unsigned p1 = pack_split(w2[ch*K2 + k + 1]);
    unsigned hi01 = __byte_perm(p0, p1, 0x5410);
    unsigned lo01 = __byte_perm(p0, p1, 0x7632);
    int chunk = k >> 5, kk = k & 31;
    g_w2img[((chunk*2 + 0)*256 + ch)*16 + (kk >> 1)] = hi01;
    g_w2img[((chunk*2 + 1)*256 + ch)*16 + (kk >> 1)] = lo01;
}

// ---------------- conv1: implicit GEMM (f32x2, 3-stage cp.async) ----------------
__global__ __launch_bounds__(256, 2)
void conv1_kernel(const float* __restrict__ Xin, const float* __restrict__ bias)
{
    constexpr int NT = K1PAD / 8;
    __shared__ __align__(16) float As[3][8][128];
    __shared__ __align__(16) float Bs[3][8][128];

    const int tid = threadIdx.x;
    const int tx  = tid & 15;
    const int ty  = tid >> 4;
    const int n0  = blockIdx.x * 128;
    const int m0  = blockIdx.y * 128;

    u64 acc[8][4];
#pragma unroll
    for (int i = 0; i < 8; ++i)
#pragma unroll
        for (int j = 0; j < 4; ++j) acc[i][j] = 0ull;

    const int ldk = tid >> 7;
    const int ldn = tid & 127;

    const int ng = n0 + ldn;
    int base;
    {
        int b   = ng / NPIX1;
        int rem = ng - b*NPIX1;
        int oy  = rem / OH1;
        int ox  = rem - oy*OH1;
        base = b*3*4096 + oy*64 + ox;
    }
    int off[4], kx[4], ky[4];
#pragma unroll
    for (int i = 0; i < 4; ++i) {
        int k0i = ldk + 2*i;
        off[i] = base + k0i; kx[i] = k0i; ky[i] = 0;
    }
    const float* aA = g_w1t + ldk*MCH + m0 + ldn;
    int kpref = 0;

    auto PREFETCH = [&](int s) {
#pragma unroll
        for (int i = 0; i < 4; ++i) {
            int k = ldk + 2*i;
            cp4u(smem_u32(&As[s][k][ldn]), aA + i*2*MCH);
            int ok = (kpref + k < K1);
            cp4(smem_u32(&Bs[s][k][ldn]), Xin + (ok ? off[i] : 0), ok ? 4 : 0);
            kx[i] += 8; off[i] += 8;
            if (kx[i] >= 9) {
                kx[i] -= 9; off[i] += 64 - 9;
                if (++ky[i] >= 9) { ky[i] -= 9; off[i] += 4096 - 9*64; }
            }
        }
        aA += 8*MCH;
        kpref += 8;
        cp_commit();
    };

    PREFETCH(0);
    PREFETCH(1);

#pragma unroll 1
    for (int it = 0; it < NT; ++it) {
        cp_wait<1>();
        __syncthreads();
        if (it + 2 < NT) PREFETCH((it + 2) % 3);
        else             cp_commit();
        const int s = it % 3;
#pragma unroll
        for (int kk = 0; kk < 8; ++kk) {
            union F4U { float4 f; u64 u[2]; };
            F4U b0, b1, a0, a1;
            b0.f = *(const float4*)&Bs[s][kk][tx*4];
            b1.f = *(const float4*)&Bs[s][kk][64 + tx*4];
            a0.f = *(const float4*)&As[s][kk][ty*4];
            a1.f = *(const float4*)&As[s][kk][64 + ty*4];
            u64 bb[4] = { b0.u[0], b0.u[1], b1.u[0], b1.u[1] };
            float av[8] = { a0.f.x, a0.f.y, a0.f.z, a0.f.w,
                            a1.f.x, a1.f.y, a1.f.z, a1.f.w };
#pragma unroll
            for (int i = 0; i < 8; ++i) {
                u64 a2 = pack2(av[i]);
#pragma unroll
                for (int j = 0; j < 4; ++j) fma2(acc[i][j], a2, bb[j]);
            }
        }
    }

    // epilogue: bias + relu + bf16-split pack
#pragma unroll
    for (int i = 0; i < 8; ++i) {
        int m = m0 + ((i < 4) ? (ty*4 + i) : (64 + ty*4 + (i - 4)));
        float bv = bias[m];
#pragma unroll
        for (int j = 0; j < 4; ++j) {
            float2 v2 = unpack2(acc[i][j]);
            int ncol = n0 + ((j < 2) ? (tx*4 + 2*j) : (64 + tx*4 + 2*(j - 2)));
#pragma unroll
            for (int e = 0; e < 2; ++e) {
                int n = ncol + e;
                float val = ((e == 0) ? v2.x : v2.y) + bv;
                val = val > 0.f ? val : 0.f;
                int b = n / NPIX1, rem = n - b*NPIX1;
                g_h1p[(b*MCH + m)*NPIX1 + rem] = pack_split(val);
            }
        }
    }
}

// ---------------- conv2: bf16-split implicit GEMM on mma.sync ----------------
// Two INDEPENDENT 128-thread half-pipelines per CTA (own A copy, own 64-ch B,
// own stages, own named barrier) -> 4 dephased pipelines per SM keep the
// tensor pipe fed while other halves ldmatrix/barrier.
__global__ __launch_bounds__(256, 2)
void conv2_mma(const float* __restrict__ bias)
{
    extern __shared__ __align__(128) char smraw[];
    const int tid  = threadIdx.x;
    const int lane = tid & 31;
    const int wid  = tid >> 5;
    const int half = tid >> 7;           // 0/1
    const int wm   = wid & 3;            // warp index within half
    const int hl   = tid & 127;
    const int m0   = blockIdx.x * 128;
    const int ch0  = blockIdx.y * 128 + half*64;
    const unsigned hb = smem_u32(smraw) + (unsigned)half*HALF_SZ;

    // ---- fill state: thread fills k-pair p for 16 rows (rbase + 8i) ----
    const int p     = hl & 15;
    const int rbase = hl >> 4;           // 0..7
    int ic, ky, kx;
    { int k0 = 2*p; ic = 0; ky = k0/9; kx = k0 - 9*ky; }
    int naddr[16];
#pragma unroll
    for (int i = 0; i < 16; ++i) {
        int nsp = m0 + rbase + 8*i;
        int b = nsp / P2, rem = nsp - b*P2;
        int oy = rem / OH2, ox = rem - oy*OH2;
        naddr[i] = b*(MCH*NPIX1) + oy*(2*OH1) + ox*2;
    }
    const unsigned sts_col = ((unsigned)(4*p)) ^ ((unsigned)(((rbase>>1)&3) << 4));

    float acc[2][8][4];
#pragma unroll
    for (int mt = 0; mt < 2; ++mt)
#pragma unroll
        for (int nt = 0; nt < 8; ++nt)
#pragma unroll
            for (int q = 0; q < 4; ++q) acc[mt][nt][q] = 0.f;

    // ---- consumer lane constants ----
    const int arow = (lane & 7) + ((lane >> 3) & 1)*8;
    const int c16  = (lane >> 4) & 1;
    const unsigned swa = (unsigned)(((arow>>1)&3) << 4);
    const unsigned a_row_off = (unsigned)((wm*32 + arow)*64);
    unsigned acolk[2];
    acolk[0] = ((unsigned)(c16*16)) ^ swa;
    acolk[1] = ((unsigned)(32 + c16*16)) ^ swa;
    const int brow = (lane & 7) + ((lane >> 4) & 1)*8;
    const int bcol = ((lane >> 3) & 1)*8;
    const unsigned boff = (unsigned)(brow*80 + bcol*2);

    int ka = 0, ka2 = 0;
    unsigned wreg[16];

    auto KADDR = [&]() {
        ka  = ic*NPIX1 + ky*OH1 + kx;
        ka2 = ka + ((kx == 8) ? ((ky == 8) ? (NPIX1 - 8*OH1 - 8) : (OH1 - 8)) : 1);
    };
    auto KADV = [&]() {
        kx += 5; ky += 3;                 // +32 k (= 3*9 + 5)
        if (kx >= 9) { kx -= 9; ++ky; }
        if (ky >= 9) { ky -= 9; ++ic; }
    };
    auto LDG_W = [&](int w) {
#pragma unroll
        for (int j = 0; j < 8; ++j) {
            int i = 8*w + j;
            wreg[2*j]   = g_h1p[naddr[i] + ka];
            wreg[2*j+1] = g_h1p[naddr[i] + ka2];
        }
    };
    auto STS_W = [&](unsigned st, int w) {
#pragma unroll
        for (int j = 0; j < 8; ++j) {
            int i = 8*w + j;
            unsigned hi01 = __byte_perm(wreg[2*j], wreg[2*j+1], 0x5410);
            unsigned lo01 = __byte_perm(wreg[2*j], wreg[2*j+1], 0x7632);
            unsigned d = st + (unsigned)((rbase + 8*i)*64) + sts_col;
            asm volatile("st.shared.b32 [%0], %1;" :: "r"(d), "r"(hi01) : "memory");
            asm volatile("st.shared.b32 [%0], %1;" :: "r"(d + A_LO_OFF), "r"(lo01) : "memory");
        }
    };
    auto B_FILL = [&](int c, unsigned st) {
#pragma unroll
        for (int it = 0; it < 4; ++it) {
            int g     = hl + 128*it;            // 0..511
            int plane = g >> 8;
            int chrow = (g >> 2) & 63;
            int j     = g & 3;
            const unsigned* src = g_w2img + (((c*2 + plane)*256) + ch0 + chrow)*16 + j*4;
            unsigned dst = st + B_HI_OFF + (unsigned)plane*5120 + (unsigned)chrow*80 + (unsigned)j*16;
            cp16(dst, src);
        }
        cp_commit();
    };
    auto MMA_KH = [&](unsigned st, int kh) {
        unsigned ah[2][4], al[2][4], bb[4];
        const unsigned ab = st + a_row_off + acolk[kh];
        ldm4(ah[0], ab);
        ldm4(ah[1], ab + 1024);
        ldm4(al[0], ab + A_LO_OFF);
        ldm4(al[1], ab + A_LO_OFF + 1024);
        const unsigned kbh = st + B_HI_OFF + boff + (unsigned)(kh*32);
#pragma unroll
        for (int j = 0; j < 4; ++j) {
            ldm4(bb, kbh + j*1280);
            mma16816(acc[0][2*j],   ah[0], bb[0], bb[1]);
            mma16816(acc[0][2*j+1], ah[0], bb[2], bb[3]);
            mma16816(acc[1][2*j],   ah[1], bb[0], bb[1]);
            mma16816(acc[1][2*j+1], ah[1], bb[2], bb[3]);
            mma16816(acc[0][2*j],   al[0], bb[0], bb[1]);
            mma16816(acc[0][2*j+1], al[0], bb[2], bb[3]);
            mma16816(acc[1][2*j],   al[1], bb[0], bb[1]);
            mma16816(acc[1][2*j+1], al[1], bb[2], bb[3]);
        }
        const unsigned kbl = kbh + (B_LO_OFF - B_HI_OFF);
#pragma unroll
        for (int j = 0; j < 4; ++j) {
            ldm4(bb, kbl + j*1280);
            mma16816(acc[0][2*j],   ah[0], bb[0], bb[1]);
            mma16816(acc[0][2*j+1], ah[0], bb[2], bb[3]);
            mma16816(acc[1][2*j],   ah[1], bb[0], bb[1]);
            mma16816(acc[1][2*j+1], ah[1], bb[2], bb[3]);
        }
    };

    const int bid = 1 + half;

    // ---- prologue: fill stage 0 of this half ----
    B_FILL(0, hb);
    KADDR();
    LDG_W(0); STS_W(hb, 0);
    LDG_W(1); STS_W(hb, 1);
    KADV();
    cp_wait<0>();
    bar_half(bid);

#pragma unroll 1
    for (int c = 0; c < NCH; ++c) {
        const unsigned st  = hb + (unsigned)(c & 1)*STAGE_SZ;
        const unsigned st2 = hb + (unsigned)((c + 1) & 1)*STAGE_SZ;
        const bool pre = (c + 1 < NCH);

        if (pre) {
            B_FILL(c + 1, st2);
            KADDR();
            LDG_W(0);
        }
        MMA_KH(st, 0);
        if (pre) {
            STS_W(st2, 0);
            LDG_W(1);
        }
        MMA_KH(st, 1);
        if (pre) {
            STS_W(st2, 1);
            KADV();
        }
        cp_wait<0>();
        bar_half(bid);
    }

    // ---- epilogue: acc + bias -> caps layout ----
#pragma unroll
    for (int mt = 0; mt < 2; ++mt) {
        int rowA = m0 + wm*32 + mt*16 + (lane >> 2);
#pragma unroll
        for (int h8 = 0; h8 < 2; ++h8) {
            int nsp = rowA + h8*8;
            int b = nsp / P2, pp = nsp - b*P2;
            long obase = ((long)(b*RR))*P2 + pp;
#pragma unroll
            for (int nt = 0; nt < 8; ++nt) {
                int chb = ch0 + nt*8 + (lane & 3)*2;
#pragma unroll
                for (int e = 0; e < 2; ++e) {
                    int ch = chb + e;
                    float v = acc[mt][nt][h8*2 + e] + bias[ch];
                    int rr = ch >> 3, dd = ch & 7;
                    g_caps[(obase + (long)rr*P2)*DD + dd] = v;
                }
            }
        }
    }
}

// ---------------- squash primary capsules (in place) ----------------
__global__ void squash_caps_kernel() {
    int v = blockIdx.x * 256 + threadIdx.x;
    if (v >= NB*RR*P2) return;
    float4 lo = *(float4*)&g_caps[v*8];
    float4 hi = *(float4*)&g_caps[v*8 + 4];
    float norm = lo.x*lo.x + lo.y*lo.y + lo.z*lo.z + lo.w*lo.w
               + hi.x*hi.x + hi.y*hi.y + hi.z*hi.z + hi.w*hi.w;
    float scale = norm / ((1.f + norm) * sqrtf(norm + 1e-8f));
    lo.x *= scale; lo.y *= scale; lo.z *= scale; lo.w *= scale;
    hi.x *= scale; hi.y *= scale; hi.z *= scale; hi.w *= scale;
    *(float4*)&g_caps[v*8]     = lo;
    *(float4*)&g_caps[v*8 + 4] = hi;
}

// ---------------- WV[b,r,c,i] = sum_o route_w[r,c,i,o] * v[b,c,o] ----------------
__global__ void wv_kernel(const float* __restrict__ route_w) {
    int idx = blockIdx.x * 128 + threadIdx.x;
    if (idx >= NB*RR*CC*DD) return;
    int b    = idx / (RR*CC*DD);
    int rem  = idx - b*(RR*CC*DD);
    int r    = rem / (CC*DD);
    int rem2 = rem - r*(CC*DD);
    int c    = rem2 / DD;
    int i    = rem2 - c*DD;
    const float* w = route_w + ((r*CC + c)*DD + i)*OO;
    const float* v = g_v + (b*CC + c)*OO;
    float acc = 0.f;
#pragma unroll
    for (int o = 0; o < OO; ++o) acc += w[o] * v[o];
    g_WV[idx] = acc;
}

// ---------------- routing pass ----------------
template<int MODE>
__global__ void pass_kernel() {
    const int b = blockIdx.x, r = blockIdx.y;
    const int tid = threadIdx.x;   // 64 threads
    __shared__ float sWV[CC*DD];
    __shared__ float sG[2][CC*DD];

    if (MODE >= 2) {
        for (int j = tid; j < CC*DD; j += 64)
            sWV[j] = g_WV[(b*RR + r)*CC*DD + j];
    }
    __syncthreads();

    float Gp[CC*DD];
#pragma unroll
    for (int j = 0; j < CC*DD; ++j) Gp[j] = 0.f;

    const float* capbase = g_caps + (size_t)(b*RR + r)*P2*DD;

#pragma unroll 1
    for (int pi = 0; pi < 9; ++pi) {
        int p = pi*64 + tid;
        float4 l0 = *(const float4*)(capbase + p*8);
        float4 l1 = *(const float4*)(capbase + p*8 + 4);
        float cv[8] = { l0.x, l0.y, l0.z, l0.w, l1.x, l1.y, l1.z, l1.w };

        float cw[CC];
        if (MODE == 1) {
#pragma unroll
            for (int c = 0; c < CC; ++c) cw[c] = 0.1f;
        } else {
            float bvv[CC];
            long bidx = ((long)b*RR*P2 + (long)r*P2 + p)*CC;
#pragma unroll
            for (int c = 0; c < CC; ++c) {
                float t = 0.f;
#pragma unroll
                for (int i = 0; i < 8; ++i) t += cv[i] * sWV[c*8 + i];
                bvv[c] = ((MODE == 3) ? g_blog[bidx + c] : 0.f) + t;
                if (MODE == 2) g_blog[bidx + c] = bvv[c];
            }
            float mx = bvv[0];
#pragma unroll
            for (int c = 1; c < CC; ++c) mx = fmaxf(mx, bvv[c]);
            float sum = 0.f;
#pragma unroll
            for (int c = 0; c < CC; ++c) { cw[c] = __expf(bvv[c] - mx); sum += cw[c]; }
            float inv = 1.f / sum;
#pragma unroll
            for (int c = 0; c < CC; ++c) cw[c] *= inv;
        }
#pragma unroll
        for (int c = 0; c < CC; ++c)
#pragma unroll
            for (int i = 0; i < 8; ++i) Gp[c*8 + i] += cw[c] * cv[i];
    }

    int wid2 = tid >> 5, lane = tid & 31;
#pragma unroll
    for (int j = 0; j < CC*DD; ++j) {
        float val = Gp[j];
#pragma unroll
        for (int s = 16; s > 0; s >>= 1) val += __shfl_xor_sync(0xffffffffu, val, s);
        if (lane == 0) sG[wid2][j] = val;
    }
    __syncthreads();
    for (int j = tid; j < CC*DD; j += 64)
        g_G[(b*RR + r)*CC*DD + j] = sG[0][j] + sG[1][j];
}

// ---------------- s = G . W ; v = squash(s) ----------------
__global__ void sv_kernel(const float* __restrict__ route_w, float* __restrict__ dout) {
    const int b = blockIdx.x;
    const int tid = threadIdx.x;     // 160 threads = (c,o)
    __shared__ float sGb[RR*CC*DD];
    __shared__ float ss[CC*OO];

    for (int j = tid; j < RR*CC*DD; j += CC*OO) sGb[j] = g_G[b*RR*CC*DD + j];
    __syncthreads();

    const int c = tid / OO, o = tid - (tid / OO)*OO;
    float s = 0.f;
#pragma unroll 1
    for (int r = 0; r < RR; ++r) {
#pragma unroll
        for (int i = 0; i < DD; ++i)
            s += sGb[(r*CC + c)*DD + i] * route_w[((r*CC + c)*DD + i)*OO + o];
    }
    ss[tid] = s;
    __syncthreads();
    float norm = 0.f;
#pragma unroll
    for (int oo = 0; oo < OO; ++oo) { float t = ss[c*OO + oo]; norm += t*t; }
    float scale = norm / ((1.f + norm) * sqrtf(norm + 1e-8f));
    float val = scale * s;
    g_v[b*CC*OO + tid] = val;
    if (dout) dout[b*CC*OO + tid] = val;
}

// ---------------- launcher ----------------
extern "C" void kernel_launch(void* const* d_in, const int* in_sizes, int n_in,
                              void* d_out, int out_size)
{
    const float* x  = (const float*)d_in[0];   // [32,3,64,64]
    const float* w1 = (const float*)d_in[1];   // [256,3,9,9]
    const float* b1 = (const float*)d_in[2];   // [256]
    const float* w2 = (const float*)d_in[3];   // [256,256,9,9]
    const float* b2 = (const float*)d_in[4];   // [256]
    const float* rw = (const float*)d_in[5];   // [32,10,8,16]
    float* out = (float*)d_out;

    static int smem_set = 0;
    if (!smem_set) {
        cudaFuncSetAttribute(conv2_mma,
                             cudaFuncAttributeMaxDynamicSharedMemorySize, CONV2_SMEM);
        smem_set = 1;
    }

    // weight prep
    wt1_kernel<<<(K1PAD*MCH + 255)/256, 256>>>(w1);
    wsplit_kernel<<<K2/2, 256>>>(w2);

    // conv1 -> g_h1p (packed bf16-split)
    conv1_kernel<<<dim3(N1/128, 2), 256>>>(x, b1);
    // conv2 -> g_caps (mma.sync tensor cores, half-CTA pipelines)
    conv2_mma<<<dim3(N2/128, 2), 256, CONV2_SMEM>>>(b2);
    // squash primary caps
    squash_caps_kernel<<<(NB*RR*P2 + 255)/256, 256>>>();

    // routing iteration 1
    pass_kernel<1><<<dim3(NB, RR), 64>>>();
    sv_kernel<<<NB, CC*OO>>>(rw, nullptr);
    // routing iteration 2
    wv_kernel<<<(NB*RR*CC*DD + 127)/128, 128>>>(rw);
    pass_kernel<2><<<dim3(NB, RR), 64>>>();
    sv_kernel<<<NB, CC*OO>>>(rw, nullptr);
    // routing iteration 3 (final)
    wv_kernel<<<(NB*RR*CC*DD + 127)/128, 128>>>(rw);
    pass_kernel<3><<<dim3(NB, RR), 64>>>();
    sv_kernel<<<NB, CC*OO>>>(rw, out);
    (void)out_size;
}

// round 13
// speedup vs baseline: 1.0673x; 1.0673x over previous
#include <cuda_runtime.h>
#include <cuda_bf16.h>

typedef unsigned long long u64;

// ---------------- packed f32x2 helpers ----------------
__device__ __forceinline__ u64 pack2(float x) {
    u64 r; unsigned u = __float_as_uint(x);
    asm("mov.b64 %0, {%1, %2};" : "=l"(r) : "r"(u), "r"(u));
    return r;
}
__device__ __forceinline__ void fma2(u64 &acc, u64 a, u64 b) {
    asm("fma.rn.f32x2 %0, %1, %2, %0;" : "+l"(acc) : "l"(a), "l"(b));
}
__device__ __forceinline__ float2 unpack2(u64 v) {
    unsigned lo, hi;
    asm("mov.b64 {%0, %1}, %2;" : "=r"(lo), "=r"(hi) : "l"(v));
    return make_float2(__uint_as_float(lo), __uint_as_float(hi));
}

// ---------------- cp.async helpers ----------------
__device__ __forceinline__ unsigned smem_u32(const void* p) {
    return (unsigned)__cvta_generic_to_shared(p);
}
__device__ __forceinline__ void cp4(unsigned dst, const float* src, int srcsize) {
    asm volatile("cp.async.ca.shared.global [%0], [%1], 4, %2;"
                 :: "r"(dst), "l"(src), "r"(srcsize));
}
__device__ __forceinline__ void cp4u(unsigned dst, const float* src) {
    asm volatile("cp.async.ca.shared.global [%0], [%1], 4;"
                 :: "r"(dst), "l"(src));
}
__device__ __forceinline__ void cp16(unsigned dst, const void* src) {
    asm volatile("cp.async.cg.shared.global [%0], [%1], 16;"
                 :: "r"(dst), "l"(src));
}
__device__ __forceinline__ void cp_commit() {
    asm volatile("cp.async.commit_group;");
}
template<int N>
__device__ __forceinline__ void cp_wait() {
    asm volatile("cp.async.wait_group %0;" :: "n"(N));
}

// ---------------- mma.sync helpers (baseline PTX, no 'a' features) ----------------
__device__ __forceinline__ void ldm4(unsigned r[4], unsigned addr) {
    asm volatile("ldmatrix.sync.aligned.m8n8.x4.shared.b16 {%0,%1,%2,%3}, [%4];"
                 : "=r"(r[0]), "=r"(r[1]), "=r"(r[2]), "=r"(r[3]) : "r"(addr));
}
__device__ __forceinline__ void mma16816(float c[4], const unsigned a[4],
                                         unsigned b0, unsigned b1) {
    asm volatile("mma.sync.aligned.m16n8k16.row.col.f32.bf16.bf16.f32 "
                 "{%0,%1,%2,%3}, {%4,%5,%6,%7}, {%8,%9}, {%0,%1,%2,%3};"
                 : "+f"(c[0]), "+f"(c[1]), "+f"(c[2]), "+f"(c[3])
                 : "r"(a[0]), "r"(a[1]), "r"(a[2]), "r"(a[3]), "r"(b0), "r"(b1));
}

// ---------------- problem constants ----------------
#define NB    32
#define OH1   56
#define NPIX1 (OH1*OH1)   // 3136
#define N1    (NB*NPIX1)  // 100352
#define K1    243
#define K1PAD 248
#define OH2   24
#define P2    (OH2*OH2)   // 576
#define N2    (NB*P2)     // 18432
#define K2    20736
#define MCH   256
#define RR    32
#define DD    8
#define CC    10
#define OO    16

// conv2 mma tiling
#define KCH    32
#define NCH    (K2/KCH)     // 648
#define OFF_ALO 10240       // bytes; A tile = 128 rows x 80B
#define OFF_BHI 20480
#define OFF_BLO 30720
#define STAGE_B 40960
#define CONV2_SMEM (2*STAGE_B)   // 80 KB

// ---------------- scratch (static device memory only) ----------------
__device__ __align__(16) unsigned g_h1p[NB*MCH*NPIX1];   // conv1 out packed (bf16hi | bf16lo<<16)
__device__ __align__(16) float    g_caps[NB*RR*P2*DD];
__device__ __align__(16) float    g_w1t[K1PAD*MCH];
__device__ __align__(16) unsigned g_w2img[NCH*2*256*16]; // [chunk][plane][ch][16 u32 = 32 bf16]
__device__ __align__(16) float    g_WV[NB*RR*CC*DD];
__device__ __align__(16) float    g_G[NB*RR*CC*DD];
__device__ __align__(16) float    g_v[NB*CC*OO];
__device__ __align__(16) float    g_blog[NB*RR*P2*CC];

// ---------------- bf16 split pack ----------------
__device__ __forceinline__ unsigned pack_split(float v) {
    __nv_bfloat16 h = __float2bfloat16(v);
    float hf = __bfloat162float(h);
    __nv_bfloat16 l = __float2bfloat16(v - hf);
    return (unsigned)__bfloat16_as_ushort(h) | ((unsigned)__bfloat16_as_ushort(l) << 16);
}

// ---------------- conv1 weight transpose ----------------
__global__ void wt1_kernel(const float* __restrict__ w) {
    int idx = blockIdx.x * 256 + threadIdx.x;
    if (idx >= K1PAD*MCH) return;
    int k = idx >> 8, m = idx & 255;
    float v = 0.f;
    if (k < K1) v = w[m*K1 + k];
    g_w1t[idx] = v;
}

// ---------------- conv2 weight split into linear image ----------------
__global__ void wsplit_kernel(const float* __restrict__ w2) {
    int t  = blockIdx.x * 256 + threadIdx.x;  // 256ch * K2/2 pairs
    int ch = t / (K2/2);
    int kp = t - ch*(K2/2);
    int k  = 2*kp;
    unsigned p0 = pack_split(w2[ch*K2 + k]);
    unsigned p1 = pack_split(w2[ch*K2 + k + 1]);
    unsigned hi01 = __byte_perm(p0, p1, 0x5410);
    unsigned lo01 = __byte_perm(p0, p1, 0x7632);
    int chunk = k >> 5, kk = k & 31;
    g_w2img[((chunk*2 + 0)*256 + ch)*16 + (kk >> 1)] = hi01;
    g_w2img[((chunk*2 + 1)*256 + ch)*16 + (kk >> 1)] = lo01;
}

// ---------------- conv1: implicit GEMM (f32x2, 3-stage cp.async) ----------------
__global__ __launch_bounds__(256, 2)
void conv1_kernel(const float* __restrict__ Xin, const float* __restrict__ bias)
{
    constexpr int NT = K1PAD / 8;
    __shared__ __align__(16) float As[3][8][128];
    __shared__ __align__(16) float Bs[3][8][128];

    const int tid = threadIdx.x;
    const int tx  = tid & 15;
    const int ty  = tid >> 4;
    const int n0  = blockIdx.x * 128;
    const int m0  = blockIdx.y * 128;

    u64 acc[8][4];
#pragma unroll
    for (int i = 0; i < 8; ++i)
#pragma unroll
        for (int j = 0; j < 4; ++j) acc[i][j] = 0ull;

    const int ldk = tid >> 7;
    const int ldn = tid & 127;

    const int ng = n0 + ldn;
    int base;
    {
        int b   = ng / NPIX1;
        int rem = ng - b*NPIX1;
        int oy  = rem / OH1;
        int ox  = rem - oy*OH1;
        base = b*3*4096 + oy*64 + ox;
    }
    int off[4], kx[4], ky[4];
#pragma unroll
    for (int i = 0; i < 4; ++i) {
        int k0i = ldk + 2*i;
        off[i] = base + k0i; kx[i] = k0i; ky[i] = 0;
    }
    const float* aA = g_w1t + ldk*MCH + m0 + ldn;
    int kpref = 0;

    auto PREFETCH = [&](int s) {
#pragma unroll
        for (int i = 0; i < 4; ++i) {
            int k = ldk + 2*i;
            cp4u(smem_u32(&As[s][k][ldn]), aA + i*2*MCH);
            int ok = (kpref + k < K1);
            cp4(smem_u32(&Bs[s][k][ldn]), Xin + (ok ? off[i] : 0), ok ? 4 : 0);
            kx[i] += 8; off[i] += 8;
            if (kx[i] >= 9) {
                kx[i] -= 9; off[i] += 64 - 9;
                if (++ky[i] >= 9) { ky[i] -= 9; off[i] += 4096 - 9*64; }
            }
        }
        aA += 8*MCH;
        kpref += 8;
        cp_commit();
    };

    PREFETCH(0);
    PREFETCH(1);

#pragma unroll 1
    for (int it = 0; it < NT; ++it) {
        cp_wait<1>();
        __syncthreads();
        if (it + 2 < NT) PREFETCH((it + 2) % 3);
        else             cp_commit();
        const int s = it % 3;
#pragma unroll
        for (int kk = 0; kk < 8; ++kk) {
            union F4U { float4 f; u64 u[2]; };
            F4U b0, b1, a0, a1;
            b0.f = *(const float4*)&Bs[s][kk][tx*4];
            b1.f = *(const float4*)&Bs[s][kk][64 + tx*4];
            a0.f = *(const float4*)&As[s][kk][ty*4];
            a1.f = *(const float4*)&As[s][kk][64 + ty*4];
            u64 bb[4] = { b0.u[0], b0.u[1], b1.u[0], b1.u[1] };
            float av[8] = { a0.f.x, a0.f.y, a0.f.z, a0.f.w,
                            a1.f.x, a1.f.y, a1.f.z, a1.f.w };
#pragma unroll
            for (int i = 0; i < 8; ++i) {
                u64 a2 = pack2(av[i]);
#pragma unroll
                for (int j = 0; j < 4; ++j) fma2(acc[i][j], a2, bb[j]);
            }
        }
    }

    // epilogue: bias + relu + bf16-split pack
#pragma unroll
    for (int i = 0; i < 8; ++i) {
        int m = m0 + ((i < 4) ? (ty*4 + i) : (64 + ty*4 + (i - 4)));
        float bv = bias[m];
#pragma unroll
        for (int j = 0; j < 4; ++j) {
            float2 v2 = unpack2(acc[i][j]);
            int ncol = n0 + ((j < 2) ? (tx*4 + 2*j) : (64 + tx*4 + 2*(j - 2)));
#pragma unroll
            for (int e = 0; e < 2; ++e) {
                int n = ncol + e;
                float val = ((e == 0) ? v2.x : v2.y) + bv;
                val = val > 0.f ? val : 0.f;
                int b = n / NPIX1, rem = n - b*NPIX1;
                g_h1p[(b*MCH + m)*NPIX1 + rem] = pack_split(val);
            }
        }
    }
}

// ---------------- conv2: bf16-split implicit GEMM on mma.sync ----------------
// D[128 spatial][128 ch] per CTA. 8 warps (4m x 2n), warp tile 32x64.
// A-fill LDGs prefetched into registers and stored post-MMA (R11 structure).
// B fragments rotate through a 2-deep register buffer so the mma of tile j
// never waits on a just-issued ldmatrix (fragments for j were loaded at j-1).
__global__ __launch_bounds__(256, 2)
void conv2_mma(const float* __restrict__ bias)
{
    extern __shared__ __align__(128) char smraw[];
    const unsigned sb = smem_u32(smraw);
    const int tid  = threadIdx.x;
    const int lane = tid & 31;
    const int wid  = tid >> 5;
    const int wm   = wid & 3;      // m-warp 0..3 (32 rows each)
    const int wn   = wid >> 2;     // n-warp 0..1 (64 ch each)
    const int m0   = blockIdx.x * 128;
    const int ch0  = blockIdx.y * 128;

    // ---- fill-state: this thread fills k-pair p for rows rbase+16*i ----
    const int p     = tid & 15;
    const int rbase = tid >> 4;
    int ic, ky, kx;
    { int k0 = 2*p; ic = 0; ky = k0/9; kx = k0 - 9*ky; }
    int naddr[8];
#pragma unroll
    for (int i = 0; i < 8; ++i) {
        int nsp = m0 + rbase + 16*i;
        int b = nsp / P2, rem = nsp - b*P2;
        int oy = rem / OH2, ox = rem - oy*OH2;
        naddr[i] = b*(MCH*NPIX1) + oy*(2*OH1) + ox*2;
    }

    float acc[2][8][4];
#pragma unroll
    for (int mt = 0; mt < 2; ++mt)
#pragma unroll
        for (int nt = 0; nt < 8; ++nt)
#pragma unroll
            for (int q = 0; q < 4; ++q) acc[mt][nt][q] = 0.f;

    // ldmatrix lane address components
    const int arow = (lane & 7) + ((lane >> 3) & 1)*8;
    const int acol = ((lane >> 4) & 1)*8;
    const int brow = (lane & 7) + ((lane >> 4) & 1)*8;
    const int bcol = ((lane >> 3) & 1)*8;
    const unsigned aoff = (unsigned)((wm*32 + arow)*80 + acol*2);
    const unsigned boff = (unsigned)(OFF_BHI + (wn*64 + brow)*80 + bcol*2);

    unsigned wreg[16];

    // load A(next chunk) pixels into registers; advances k-state
    auto LDG_A = [&]() {
        int ka  = ic*NPIX1 + ky*OH1 + kx;
        int ka2 = ka + ((kx == 8) ? ((ky == 8) ? (NPIX1 - 8*OH1 - 8) : (OH1 - 8)) : 1);
#pragma unroll
        for (int i = 0; i < 8; ++i) {
            wreg[2*i]   = g_h1p[naddr[i] + ka];
            wreg[2*i+1] = g_h1p[naddr[i] + ka2];
        }
        kx += 5; ky += 3;                 // advance k by 32 (= 3*9 + 5)
        if (kx >= 9) { kx -= 9; ++ky; }
        if (ky >= 9) { ky -= 9; ++ic; }
    };
    // split + store the prefetched A registers into stage st
    auto STS_A = [&](unsigned st) {
#pragma unroll
        for (int i = 0; i < 8; ++i) {
            unsigned hi01 = __byte_perm(wreg[2*i], wreg[2*i+1], 0x5410);
            unsigned lo01 = __byte_perm(wreg[2*i], wreg[2*i+1], 0x7632);
            unsigned d = st + (unsigned)(rbase + 16*i)*80 + 4u*p;
            asm volatile("st.shared.b32 [%0], %1;" :: "r"(d), "r"(hi01) : "memory");
            asm volatile("st.shared.b32 [%0], %1;" :: "r"(d + OFF_ALO), "r"(lo01) : "memory");
        }
    };
    // B weights via cp.async from linear pre-split image
    auto B_FILL = [&](int c, unsigned st) {
#pragma unroll
        for (int it = 0; it < 4; ++it) {
            int g     = tid + 256*it;
            int plane = g >> 9;
            int chrow = (g >> 2) & 127;
            int j     = g & 3;
            const unsigned* src = g_w2img + (((c*2 + plane)*256) + ch0 + chrow)*16 + j*4;
            unsigned dst = st + (plane ? OFF_BLO : OFF_BHI) + (unsigned)chrow*80 + j*16;
            cp16(dst, src);
        }
        cp_commit();
    };

    // one kh phase with rotating 2-deep B fragment buffers
    auto MMA_KH = [&](unsigned st, int kh) {
        const unsigned ka_ = st + aoff + kh*32;
        const unsigned kb_ = st + boff + kh*32;
        unsigned ah[2][4], al[2][4];
        unsigned bh[2][4], bl[2][4];
        ldm4(ah[0], ka_);
        ldm4(ah[1], ka_ + 1280);
        ldm4(al[0], ka_ + OFF_ALO);
        ldm4(al[1], ka_ + OFF_ALO + 1280);
        ldm4(bh[0], kb_);
        ldm4(bl[0], kb_ + (OFF_BLO - OFF_BHI));
#pragma unroll
        for (int j = 0; j < 4; ++j) {
            const int cur = j & 1, nxt = cur ^ 1;
            if (j < 3) {
                ldm4(bh[nxt], kb_ + (j+1)*1280);
                ldm4(bl[nxt], kb_ + (OFF_BLO - OFF_BHI) + (j+1)*1280);
            }
            // 12 mma on fragments loaded one iteration ago
            mma16816(acc[0][2*j],   ah[0], bh[cur][0], bh[cur][1]);
            mma16816(acc[0][2*j+1], ah[0], bh[cur][2], bh[cur][3]);
            mma16816(acc[1][2*j],   ah[1], bh[cur][0], bh[cur][1]);
            mma16816(acc[1][2*j+1], ah[1], bh[cur][2], bh[cur][3]);
            mma16816(acc[0][2*j],   al[0], bh[cur][0], bh[cur][1]);
            mma16816(acc[0][2*j+1], al[0], bh[cur][2], bh[cur][3]);
            mma16816(acc[1][2*j],   al[1], bh[cur][0], bh[cur][1]);
            mma16816(acc[1][2*j+1], al[1], bh[cur][2], bh[cur][3]);
            mma16816(acc[0][2*j],   ah[0], bl[cur][0], bl[cur][1]);
            mma16816(acc[0][2*j+1], ah[0], bl[cur][2], bl[cur][3]);
            mma16816(acc[1][2*j],   ah[1], bl[cur][0], bl[cur][1]);
            mma16816(acc[1][2*j+1], ah[1], bl[cur][2], bl[cur][3]);
        }
    };

    // prologue: fill stage 0
    LDG_A();
    B_FILL(0, sb);
    STS_A(sb);
    cp_wait<0>();
    __syncthreads();

#pragma unroll 1
    for (int c = 0; c < NCH; ++c) {
        const unsigned st  = sb + (unsigned)(c & 1)*STAGE_B;
        const unsigned st2 = sb + (unsigned)((c + 1) & 1)*STAGE_B;
        const bool pre = (c + 1 < NCH);

        if (pre) {
            LDG_A();            // latency covered by the MMA section below
            B_FILL(c + 1, st2);
        }
        MMA_KH(st, 0);
        if (pre) STS_A(st2);    // writes the other buffer; safe pre-sync
        MMA_KH(st, 1);
        cp_wait<0>();           // B(c+1) landed
        __syncthreads();        // stage c free, stage c+1 visible
    }

    // ---- epilogue: acc + bias -> caps layout ----
#pragma unroll
    for (int mt = 0; mt < 2; ++mt) {
        int rowA = m0 + wm*32 + mt*16 + (lane >> 2);
#pragma unroll
        for (int half = 0; half < 2; ++half) {
            int nsp = rowA + half*8;
            int b = nsp / P2, pp = nsp - b*P2;
            long obase = ((long)(b*RR))*P2 + pp;
#pragma unroll
            for (int nt = 0; nt < 8; ++nt) {
                int chb = ch0 + wn*64 + nt*8 + (lane & 3)*2;
#pragma unroll
                for (int e = 0; e < 2; ++e) {
                    int ch = chb + e;
                    float v = acc[mt][nt][half*2 + e] + bias[ch];
                    int rr = ch >> 3, dd = ch & 7;
                    g_caps[(obase + (long)rr*P2)*DD + dd] = v;
                }
            }
        }
    }
}

// ---------------- squash primary capsules (in place) ----------------
__global__ void squash_caps_kernel() {
    int v = blockIdx.x * 256 + threadIdx.x;
    if (v >= NB*RR*P2) return;
    float4 lo = *(float4*)&g_caps[v*8];
    float4 hi = *(float4*)&g_caps[v*8 + 4];
    float norm = lo.x*lo.x + lo.y*lo.y + lo.z*lo.z + lo.w*lo.w
               + hi.x*hi.x + hi.y*hi.y + hi.z*hi.z + hi.w*hi.w;
    float scale = norm / ((1.f + norm) * sqrtf(norm + 1e-8f));
    lo.x *= scale; lo.y *= scale; lo.z *= scale; lo.w *= scale;
    hi.x *= scale; hi.y *= scale; hi.z *= scale; hi.w *= scale;
    *(float4*)&g_caps[v*8]     = lo;
    *(float4*)&g_caps[v*8 + 4] = hi;
}

// ---------------- WV[b,r,c,i] = sum_o route_w[r,c,i,o] * v[b,c,o] ----------------
__global__ void wv_kernel(const float* __restrict__ route_w) {
    int idx = blockIdx.x * 128 + threadIdx.x;
    if (idx >= NB*RR*CC*DD) return;
    int b    = idx / (RR*CC*DD);
    int rem  = idx - b*(RR*CC*DD);
    int r    = rem / (CC*DD);
    int rem2 = rem - r*(CC*DD);
    int c    = rem2 / DD;
    int i    = rem2 - c*DD;
    const float* w = route_w + ((r*CC + c)*DD + i)*OO;
    const float* v = g_v + (b*CC + c)*OO;
    float acc = 0.f;
#pragma unroll
    for (int o = 0; o < OO; ++o) acc += w[o] * v[o];
    g_WV[idx] = acc;
}

// ---------------- routing pass ----------------
template<int MODE>
__global__ void pass_kernel() {
    const int b = blockIdx.x, r = blockIdx.y;
    const int tid = threadIdx.x;   // 64 threads
    __shared__ float sWV[CC*DD];
    __shared__ float sG[2][CC*DD];

    if (MODE >= 2) {
        for (int j = tid; j < CC*DD; j += 64)
            sWV[j] = g_WV[(b*RR + r)*CC*DD + j];
    }
    __syncthreads();

    float Gp[CC*DD];
#pragma unroll
    for (int j = 0; j < CC*DD; ++j) Gp[j] = 0.f;

    const float* capbase = g_caps + (size_t)(b*RR + r)*P2*DD;

#pragma unroll 1
    for (int pi = 0; pi < 9; ++pi) {
        int p = pi*64 + tid;
        float4 l0 = *(const float4*)(capbase + p*8);
        float4 l1 = *(const float4*)(capbase + p*8 + 4);
        float cv[8] = { l0.x, l0.y, l0.z, l0.w, l1.x, l1.y, l1.z, l1.w };

        float cw[CC];
        if (MODE == 1) {
#pragma unroll
            for (int c = 0; c < CC; ++c) cw[c] = 0.1f;
        } else {
            float bvv[CC];
            long bidx = ((long)b*RR*P2 + (long)r*P2 + p)*CC;
#pragma unroll
            for (int c = 0; c < CC; ++c) {
                float t = 0.f;
#pragma unroll
                for (int i = 0; i < 8; ++i) t += cv[i] * sWV[c*8 + i];
                bvv[c] = ((MODE == 3) ? g_blog[bidx + c] : 0.f) + t;
                if (MODE == 2) g_blog[bidx + c] = bvv[c];
            }
            float mx = bvv[0];
#pragma unroll
            for (int c = 1; c < CC; ++c) mx = fmaxf(mx, bvv[c]);
            float sum = 0.f;
#pragma unroll
            for (int c = 0; c < CC; ++c) { cw[c] = __expf(bvv[c] - mx); sum += cw[c]; }
            float inv = 1.f / sum;
#pragma unroll
            for (int c = 0; c < CC; ++c) cw[c] *= inv;
        }
#pragma unroll
        for (int c = 0; c < CC; ++c)
#pragma unroll
            for (int i = 0; i < 8; ++i) Gp[c*8 + i] += cw[c] * cv[i];
    }

    int wid2 = tid >> 5, lane = tid & 31;
#pragma unroll
    for (int j = 0; j < CC*DD; ++j) {
        float val = Gp[j];
#pragma unroll
        for (int s = 16; s > 0; s >>= 1) val += __shfl_xor_sync(0xffffffffu, val, s);
        if (lane == 0) sG[wid2][j] = val;
    }
    __syncthreads();
    for (int j = tid; j < CC*DD; j += 64)
        g_G[(b*RR + r)*CC*DD + j] = sG[0][j] + sG[1][j];
}

// ---------------- s = G . W ; v = squash(s) ----------------
__global__ void sv_kernel(const float* __restrict__ route_w, float* __restrict__ dout) {
    const int b = blockIdx.x;
    const int tid = threadIdx.x;     // 160 threads = (c,o)
    __shared__ float sGb[RR*CC*DD];
    __shared__ float ss[CC*OO];

    for (int j = tid; j < RR*CC*DD; j += CC*OO) sGb[j] = g_G[b*RR*CC*DD + j];
    __syncthreads();

    const int c = tid / OO, o = tid - (tid / OO)*OO;
    float s = 0.f;
#pragma unroll 1
    for (int r = 0; r < RR; ++r) {
#pragma unroll
        for (int i = 0; i < DD; ++i)
            s += sGb[(r*CC + c)*DD + i] * route_w[((r*CC + c)*DD + i)*OO + o];
    }
    ss[tid] = s;
    __syncthreads();
    float norm = 0.f;
#pragma unroll
    for (int oo = 0; oo < OO; ++oo) { float t = ss[c*OO + oo]; norm += t*t; }
    float scale = norm / ((1.f + norm) * sqrtf(norm + 1e-8f));
    float val = scale * s;
    g_v[b*CC*OO + tid] = val;
    if (dout) dout[b*CC*OO + tid] = val;
}

// ---------------- launcher ----------------
extern "C" void kernel_launch(void* const* d_in, const int* in_sizes, int n_in,
                              void* d_out, int out_size)
{
    const float* x  = (const float*)d_in[0];   // [32,3,64,64]
    const float* w1 = (const float*)d_in[1];   // [256,3,9,9]
    const float* b1 = (const float*)d_in[2];   // [256]
    const float* w2 = (const float*)d_in[3];   // [256,256,9,9]
    const float* b2 = (const float*)d_in[4];   // [256]
    const float* rw = (const float*)d_in[5];   // [32,10,8,16]
    float* out = (float*)d_out;

    static int smem_set = 0;
    if (!smem_set) {
        cudaFuncSetAttribute(conv2_mma,
                             cudaFuncAttributeMaxDynamicSharedMemorySize, CONV2_SMEM);
        smem_set = 1;
    }

    // weight prep
    wt1_kernel<<<(K1PAD*MCH + 255)/256, 256>>>(w1);
    wsplit_kernel<<<K2/2, 256>>>(w2);

    // conv1 -> g_h1p (packed bf16-split)
    conv1_kernel<<<dim3(N1/128, 2), 256>>>(x, b1);
    // conv2 -> g_caps (mma.sync tensor cores)
    conv2_mma<<<dim3(N2/128, 2), 256, CONV2_SMEM>>>(b2);
    // squash primary caps
    squash_caps_kernel<<<(NB*RR*P2 + 255)/256, 256>>>();

    // routing iteration 1
    pass_kernel<1><<<dim3(NB, RR), 64>>>();
    sv_kernel<<<NB, CC*OO>>>(rw, nullptr);
    // routing iteration 2
    wv_kernel<<<(NB*RR*CC*DD + 127)/128, 128>>>(rw);
    pass_kernel<2><<<dim3(NB, RR), 64>>>();
    sv_kernel<<<NB, CC*OO>>>(rw, nullptr);
    // routing iteration 3 (final)
    wv_kernel<<<(NB*RR*CC*DD + 127)/128, 128>>>(rw);
    pass_kernel<3><<<dim3(NB, RR), 64>>>();
    sv_kernel<<<NB, CC*OO>>>(rw, out);
    (void)out_size;
}

// round 14
// speedup vs baseline: 1.1541x; 1.0814x over previous
#include <cuda_runtime.h>
#include <cuda_bf16.h>

typedef unsigned long long u64;

// ---------------- cp.async helpers ----------------
__device__ __forceinline__ unsigned smem_u32(const void* p) {
    return (unsigned)__cvta_generic_to_shared(p);
}
__device__ __forceinline__ void cp16(unsigned dst, const void* src) {
    asm volatile("cp.async.cg.shared.global [%0], [%1], 16;"
                 :: "r"(dst), "l"(src));
}
__device__ __forceinline__ void cp_commit() {
    asm volatile("cp.async.commit_group;");
}
template<int N>
__device__ __forceinline__ void cp_wait() {
    asm volatile("cp.async.wait_group %0;" :: "n"(N));
}

// ---------------- mma.sync helpers (baseline PTX, no 'a' features) ----------------
__device__ __forceinline__ void ldm4(unsigned r[4], unsigned addr) {
    asm volatile("ldmatrix.sync.aligned.m8n8.x4.shared.b16 {%0,%1,%2,%3}, [%4];"
                 : "=r"(r[0]), "=r"(r[1]), "=r"(r[2]), "=r"(r[3]) : "r"(addr));
}
__device__ __forceinline__ void mma16816(float c[4], const unsigned a[4],
                                         unsigned b0, unsigned b1) {
    asm volatile("mma.sync.aligned.m16n8k16.row.col.f32.bf16.bf16.f32 "
                 "{%0,%1,%2,%3}, {%4,%5,%6,%7}, {%8,%9}, {%0,%1,%2,%3};"
                 : "+f"(c[0]), "+f"(c[1]), "+f"(c[2]), "+f"(c[3])
                 : "r"(a[0]), "r"(a[1]), "r"(a[2]), "r"(a[3]), "r"(b0), "r"(b1));
}

// ---------------- problem constants ----------------
#define NB    32
#define OH1   56
#define NPIX1 (OH1*OH1)   // 3136
#define N1    (NB*NPIX1)  // 100352
#define K1    243
#define OH2   24
#define P2    (OH2*OH2)   // 576
#define N2    (NB*P2)     // 18432
#define K2    20736
#define MCH   256
#define RR    32
#define DD    8
#define CC    10
#define OO    16

// mma tiling
#define KCH    32
#define NCH2   (K2/KCH)     // 648
#define NCH1   8            // 243 padded to 256
#define OFF_ALO 10240       // bytes; A tile = 128 rows x 80B
#define OFF_BHI 20480
#define OFF_BLO 30720
#define STAGE_B 40960
#define CONV_SMEM (2*STAGE_B)   // 80 KB

// ---------------- scratch (static device memory only) ----------------
__device__ __align__(16) unsigned g_xp[NB*3*64*64];      // x packed (bf16hi | bf16lo<<16)
__device__ __align__(16) unsigned g_h1p[NB*MCH*NPIX1];   // conv1 out packed
__device__ __align__(16) float    g_caps[NB*RR*P2*DD];
__device__ __align__(16) unsigned g_w1img[NCH1*2*256*16]; // conv1 weights image
__device__ __align__(16) unsigned g_w2img[NCH2*2*256*16]; // conv2 weights image
__device__ __align__(16) float    g_WV[NB*RR*CC*DD];
__device__ __align__(16) float    g_G[NB*RR*CC*DD];
__device__ __align__(16) float    g_v[NB*CC*OO];
__device__ __align__(16) float    g_blog[NB*RR*P2*CC];

// ---------------- bf16 split pack ----------------
__device__ __forceinline__ unsigned pack_split(float v) {
    __nv_bfloat16 h = __float2bfloat16(v);
    float hf = __bfloat162float(h);
    __nv_bfloat16 l = __float2bfloat16(v - hf);
    return (unsigned)__bfloat16_as_ushort(h) | ((unsigned)__bfloat16_as_ushort(l) << 16);
}

// ---------------- input pack ----------------
__global__ void xpack_kernel(const float* __restrict__ x) {
    int idx = blockIdx.x * 256 + threadIdx.x;
    if (idx >= NB*3*64*64) return;
    g_xp[idx] = pack_split(x[idx]);
}

// ---------------- weight split into per-chunk linear images ----------------
__global__ void w1split_kernel(const float* __restrict__ w1) {
    int t  = blockIdx.x * 256 + threadIdx.x;   // 256 ch * 128 k-pairs
    if (t >= 256*128) return;
    int ch = t >> 7;
    int kp = t & 127;
    int k  = 2*kp;
    unsigned p0 = (k   < K1) ? pack_split(w1[ch*K1 + k])     : 0u;
    unsigned p1 = (k+1 < K1) ? pack_split(w1[ch*K1 + k + 1]) : 0u;
    unsigned hi01 = __byte_perm(p0, p1, 0x5410);
    unsigned lo01 = __byte_perm(p0, p1, 0x7632);
    int chunk = k >> 5, kk = k & 31;
    g_w1img[((chunk*2 + 0)*256 + ch)*16 + (kk >> 1)] = hi01;
    g_w1img[((chunk*2 + 1)*256 + ch)*16 + (kk >> 1)] = lo01;
}
__global__ void w2split_kernel(const float* __restrict__ w2) {
    int t  = blockIdx.x * 256 + threadIdx.x;  // 256ch * K2/2 pairs
    int ch = t / (K2/2);
    int kp = t - ch*(K2/2);
    int k  = 2*kp;
    unsigned p0 = pack_split(w2[ch*K2 + k]);
    unsigned p1 = pack_split(w2[ch*K2 + k + 1]);
    unsigned hi01 = __byte_perm(p0, p1, 0x5410);
    unsigned lo01 = __byte_perm(p0, p1, 0x7632);
    int chunk = k >> 5, kk = k & 31;
    g_w2img[((chunk*2 + 0)*256 + ch)*16 + (kk >> 1)] = hi01;
    g_w2img[((chunk*2 + 1)*256 + ch)*16 + (kk >> 1)] = lo01;
}

// ---------------- conv: bf16-split implicit GEMM on mma.sync ----------------
// D[128 spatial][128 ch] per CTA. 8 warps (4m x 2n), warp tile 32x64.
// CONV==1: A = im2col(g_xp) (stride 1, 3 ch, 64x64), B = g_w1img, out = g_h1p (relu+pack)
// CONV==2: A = im2col(g_h1p) (stride 2, 256 ch, 56x56), B = g_w2img, out = g_caps
template<int CONV>
__global__ __launch_bounds__(256, 2)
void conv_mma(const float* __restrict__ bias)
{
    constexpr int NCHT  = (CONV == 1) ? NCH1 : NCH2;
    constexpr int CHSTR = (CONV == 1) ? 4096 : NPIX1;  // input channel stride
    constexpr int IW    = (CONV == 1) ? 64 : OH1;      // input row stride
    const unsigned* img = (CONV == 1) ? g_w1img : g_w2img;
    const unsigned* act = (CONV == 1) ? g_xp   : g_h1p;

    extern __shared__ __align__(128) char smraw[];
    const unsigned sb = smem_u32(smraw);
    const int tid  = threadIdx.x;
    const int lane = tid & 31;
    const int wid  = tid >> 5;
    const int wm   = wid & 3;      // m-warp 0..3 (32 rows each)
    const int wn   = wid >> 2;     // n-warp 0..1 (64 ch each)
    const int m0   = blockIdx.x * 128;
    const int ch0  = blockIdx.y * 128;

    // ---- fill-state: this thread fills k-pair p for rows rbase+16*i ----
    const int p     = tid & 15;
    const int rbase = tid >> 4;
    int ic, ky, kx, kglob;
    { kglob = 2*p; ic = 0; ky = kglob/9; kx = kglob - 9*ky; }
    int naddr[8];
#pragma unroll
    for (int i = 0; i < 8; ++i) {
        int nsp = m0 + rbase + 16*i;
        if (CONV == 1) {
            int b = nsp / NPIX1, pix = nsp - b*NPIX1;
            int oy = pix / OH1, ox = pix - oy*OH1;
            naddr[i] = b*(3*4096) + oy*64 + ox;
        } else {
            int b = nsp / P2, rem = nsp - b*P2;
            int oy = rem / OH2, ox = rem - oy*OH2;
            naddr[i] = b*(MCH*NPIX1) + oy*(2*OH1) + ox*2;
        }
    }

    float acc[2][8][4];
#pragma unroll
    for (int mt = 0; mt < 2; ++mt)
#pragma unroll
        for (int nt = 0; nt < 8; ++nt)
#pragma unroll
            for (int q = 0; q < 4; ++q) acc[mt][nt][q] = 0.f;

    // ldmatrix lane address components
    const int arow = (lane & 7) + ((lane >> 3) & 1)*8;
    const int acol = ((lane >> 4) & 1)*8;
    const int brow = (lane & 7) + ((lane >> 4) & 1)*8;
    const int bcol = ((lane >> 3) & 1)*8;
    const unsigned aoff = (unsigned)((wm*32 + arow)*80 + acol*2);
    const unsigned boff = (unsigned)(OFF_BHI + (wn*64 + brow)*80 + bcol*2);

    unsigned wreg[16];

    // load A(next chunk) pixels into registers; advances k-state
    auto LDG_A = [&]() {
        int ka  = ic*CHSTR + ky*IW + kx;
        int ka2 = ka + ((kx == 8) ? ((ky == 8) ? (CHSTR - 8*IW - 8) : (IW - 8)) : 1);
        if (CONV == 1) {
            const bool v0 = (kglob < K1), v1 = (kglob + 1 < K1);
            const int o0 = v0 ? ka : 0, o1 = v1 ? ka2 : 0;
#pragma unroll
            for (int i = 0; i < 8; ++i) {
                unsigned w0 = act[naddr[i] + o0];
                unsigned w1v = act[naddr[i] + o1];
                wreg[2*i]   = v0 ? w0  : 0u;
                wreg[2*i+1] = v1 ? w1v : 0u;
            }
        } else {
#pragma unroll
            for (int i = 0; i < 8; ++i) {
                wreg[2*i]   = act[naddr[i] + ka];
                wreg[2*i+1] = act[naddr[i] + ka2];
            }
        }
        kglob += 32;
        kx += 5; ky += 3;                 // advance k by 32 (= 3*9 + 5)
        if (kx >= 9) { kx -= 9; ++ky; }
        if (ky >= 9) { ky -= 9; ++ic; }
    };
    // split + store the prefetched A registers into stage st
    auto STS_A = [&](unsigned st) {
#pragma unroll
        for (int i = 0; i < 8; ++i) {
            unsigned hi01 = __byte_perm(wreg[2*i], wreg[2*i+1], 0x5410);
            unsigned lo01 = __byte_perm(wreg[2*i], wreg[2*i+1], 0x7632);
            unsigned d = st + (unsigned)(rbase + 16*i)*80 + 4u*p;
            asm volatile("st.shared.b32 [%0], %1;" :: "r"(d), "r"(hi01) : "memory");
            asm volatile("st.shared.b32 [%0], %1;" :: "r"(d + OFF_ALO), "r"(lo01) : "memory");
        }
    };
    // B weights via cp.async from linear pre-split image
    auto B_FILL = [&](int c, unsigned st) {
#pragma unroll
        for (int it = 0; it < 4; ++it) {
            int g     = tid + 256*it;
            int plane = g >> 9;
            int chrow = (g >> 2) & 127;
            int j     = g & 3;
            const unsigned* src = img + (((c*2 + plane)*256) + ch0 + chrow)*16 + j*4;
            unsigned dst = st + (plane ? OFF_BLO : OFF_BHI) + (unsigned)chrow*80 + j*16;
            cp16(dst, src);
        }
        cp_commit();
    };

    // one kh phase: 12 ldm4 + 48 mma (R11 structure — ptxas schedules best)
    auto MMA_KH = [&](unsigned st, int kh) {
        const unsigned ka_ = st + aoff + kh*32;
        const unsigned kb_ = st + boff + kh*32;
        unsigned ah[2][4], al[2][4], bb[4];
        ldm4(ah[0], ka_);
        ldm4(ah[1], ka_ + 1280);
        ldm4(al[0], ka_ + OFF_ALO);
        ldm4(al[1], ka_ + OFF_ALO + 1280);
#pragma unroll
        for (int j = 0; j < 4; ++j) {
            ldm4(bb, kb_ + j*1280);
            mma16816(acc[0][2*j],   ah[0], bb[0], bb[1]);
            mma16816(acc[0][2*j+1], ah[0], bb[2], bb[3]);
            mma16816(acc[1][2*j],   ah[1], bb[0], bb[1]);
            mma16816(acc[1][2*j+1], ah[1], bb[2], bb[3]);
            mma16816(acc[0][2*j],   al[0], bb[0], bb[1]);
            mma16816(acc[0][2*j+1], al[0], bb[2], bb[3]);
            mma16816(acc[1][2*j],   al[1], bb[0], bb[1]);
            mma16816(acc[1][2*j+1], al[1], bb[2], bb[3]);
        }
#pragma unroll
        for (int j = 0; j < 4; ++j) {
            ldm4(bb, kb_ + (OFF_BLO - OFF_BHI) + j*1280);
            mma16816(acc[0][2*j],   ah[0], bb[0], bb[1]);
            mma16816(acc[0][2*j+1], ah[0], bb[2], bb[3]);
            mma16816(acc[1][2*j],   ah[1], bb[0], bb[1]);
            mma16816(acc[1][2*j+1], ah[1], bb[2], bb[3]);
        }
    };

    // prologue: fill stage 0
    LDG_A();
    B_FILL(0, sb);
    STS_A(sb);
    cp_wait<0>();
    __syncthreads();

#pragma unroll 1
    for (int c = 0; c < NCHT; ++c) {
        const unsigned st  = sb + (unsigned)(c & 1)*STAGE_B;
        const unsigned st2 = sb + (unsigned)((c + 1) & 1)*STAGE_B;
        const bool pre = (c + 1 < NCHT);

        if (pre) {
            LDG_A();            // latency covered by the MMA section below
            B_FILL(c + 1, st2);
        }
        MMA_KH(st, 0);
        if (pre) STS_A(st2);    // writes the other buffer; safe pre-sync
        MMA_KH(st, 1);
        cp_wait<0>();           // B(c+1) landed
        __syncthreads();        // stage c free, stage c+1 visible
    }

    // ---- epilogue ----
#pragma unroll
    for (int mt = 0; mt < 2; ++mt) {
        int rowA = m0 + wm*32 + mt*16 + (lane >> 2);
#pragma unroll
        for (int half = 0; half < 2; ++half) {
            int nsp = rowA + half*8;
            if (CONV == 1) {
                int b = nsp / NPIX1, pix = nsp - b*NPIX1;
                size_t obase = (size_t)b*MCH*NPIX1 + pix;
#pragma unroll
                for (int nt = 0; nt < 8; ++nt) {
                    int chb = ch0 + wn*64 + nt*8 + (lane & 3)*2;
#pragma unroll
                    for (int e = 0; e < 2; ++e) {
                        int ch = chb + e;
                        float v = acc[mt][nt][half*2 + e] + bias[ch];
                        v = v > 0.f ? v : 0.f;
                        g_h1p[obase + (size_t)ch*NPIX1] = pack_split(v);
                    }
                }
            } else {
                int b = nsp / P2, pp = nsp - b*P2;
                long obase = ((long)(b*RR))*P2 + pp;
#pragma unroll
                for (int nt = 0; nt < 8; ++nt) {
                    int chb = ch0 + wn*64 + nt*8 + (lane & 3)*2;
#pragma unroll
                    for (int e = 0; e < 2; ++e) {
                        int ch = chb + e;
                        float v = acc[mt][nt][half*2 + e] + bias[ch];
                        int rr = ch >> 3, dd = ch & 7;
                        g_caps[(obase + (long)rr*P2)*DD + dd] = v;
                    }
                }
            }
        }
    }
}

// ---------------- squash primary capsules (in place) ----------------
__global__ void squash_caps_kernel() {
    int v = blockIdx.x * 256 + threadIdx.x;
    if (v >= NB*RR*P2) return;
    float4 lo = *(float4*)&g_caps[v*8];
    float4 hi = *(float4*)&g_caps[v*8 + 4];
    float norm = lo.x*lo.x + lo.y*lo.y + lo.z*lo.z + lo.w*lo.w
               + hi.x*hi.x + hi.y*hi.y + hi.z*hi.z + hi.w*hi.w;
    float scale = norm / ((1.f + norm) * sqrtf(norm + 1e-8f));
    lo.x *= scale; lo.y *= scale; lo.z *= scale; lo.w *= scale;
    hi.x *= scale; hi.y *= scale; hi.z *= scale; hi.w *= scale;
    *(float4*)&g_caps[v*8]     = lo;
    *(float4*)&g_caps[v*8 + 4] = hi;
}

// ---------------- WV[b,r,c,i] = sum_o route_w[r,c,i,o] * v[b,c,o] ----------------
__global__ void wv_kernel(const float* __restrict__ route_w) {
    int idx = blockIdx.x * 128 + threadIdx.x;
    if (idx >= NB*RR*CC*DD) return;
    int b    = idx / (RR*CC*DD);
    int rem  = idx - b*(RR*CC*DD);
    int r    = rem / (CC*DD);
    int rem2 = rem - r*(CC*DD);
    int c    = rem2 / DD;
    int i    = rem2 - c*DD;
    const float* w = route_w + ((r*CC + c)*DD + i)*OO;
    const float* v = g_v + (b*CC + c)*OO;
    float acc = 0.f;
#pragma unroll
    for (int o = 0; o < OO; ++o) acc += w[o] * v[o];
    g_WV[idx] = acc;
}

// ---------------- routing pass ----------------
template<int MODE>
__global__ void pass_kernel() {
    const int b = blockIdx.x, r = blockIdx.y;
    const int tid = threadIdx.x;   // 64 threads
    __shared__ float sWV[CC*DD];
    __shared__ float sG[2][CC*DD];

    if (MODE >= 2) {
        for (int j = tid; j < CC*DD; j += 64)
            sWV[j] = g_WV[(b*RR + r)*CC*DD + j];
    }
    __syncthreads();

    float Gp[CC*DD];
#pragma unroll
    for (int j = 0; j < CC*DD; ++j) Gp[j] = 0.f;

    const float* capbase = g_caps + (size_t)(b*RR + r)*P2*DD;

#pragma unroll 1
    for (int pi = 0; pi < 9; ++pi) {
        int p = pi*64 + tid;
        float4 l0 = *(const float4*)(capbase + p*8);
        float4 l1 = *(const float4*)(capbase + p*8 + 4);
        float cv[8] = { l0.x, l0.y, l0.z, l0.w, l1.x, l1.y, l1.z, l1.w };

        float cw[CC];
        if (MODE == 1) {
#pragma unroll
            for (int c = 0; c < CC; ++c) cw[c] = 0.1f;
        } else {
            float bvv[CC];
            long bidx = ((long)b*RR*P2 + (long)r*P2 + p)*CC;
#pragma unroll
            for (int c = 0; c < CC; ++c) {
                float t = 0.f;
#pragma unroll
                for (int i = 0; i < 8; ++i) t += cv[i] * sWV[c*8 + i];
                bvv[c] = ((MODE == 3) ? g_blog[bidx + c] : 0.f) + t;
                if (MODE == 2) g_blog[bidx + c] = bvv[c];
            }
            float mx = bvv[0];
#pragma unroll
            for (int c = 1; c < CC; ++c) mx = fmaxf(mx, bvv[c]);
            float sum = 0.f;
#pragma unroll
            for (int c = 0; c < CC; ++c) { cw[c] = __expf(bvv[c] - mx); sum += cw[c]; }
            float inv = 1.f / sum;
#pragma unroll
            for (int c = 0; c < CC; ++c) cw[c] *= inv;
        }
#pragma unroll
        for (int c = 0; c < CC; ++c)
#pragma unroll
            for (int i = 0; i < 8; ++i) Gp[c*8 + i] += cw[c] * cv[i];
    }

    int wid2 = tid >> 5, lane = tid & 31;
#pragma unroll
    for (int j = 0; j < CC*DD; ++j) {
        float val = Gp[j];
#pragma unroll
        for (int s = 16; s > 0; s >>= 1) val += __shfl_xor_sync(0xffffffffu, val, s);
        if (lane == 0) sG[wid2][j] = val;
    }
    __syncthreads();
    for (int j = tid; j < CC*DD; j += 64)
        g_G[(b*RR + r)*CC*DD + j] = sG[0][j] + sG[1][j];
}

// ---------------- s = G . W ; v = squash(s) ----------------
__global__ void sv_kernel(const float* __restrict__ route_w, float* __restrict__ dout) {
    const int b = blockIdx.x;
    const int tid = threadIdx.x;     // 160 threads = (c,o)
    __shared__ float sGb[RR*CC*DD];
    __shared__ float ss[CC*OO];

    for (int j = tid; j < RR*CC*DD; j += CC*OO) sGb[j] = g_G[b*RR*CC*DD + j];
    __syncthreads();

    const int c = tid / OO, o = tid - (tid / OO)*OO;
    float s = 0.f;
#pragma unroll 1
    for (int r = 0; r < RR; ++r) {
#pragma unroll
        for (int i = 0; i < DD; ++i)
            s += sGb[(r*CC + c)*DD + i] * route_w[((r*CC + c)*DD + i)*OO + o];
    }
    ss[tid] = s;
    __syncthreads();
    float norm = 0.f;
#pragma unroll
    for (int oo = 0; oo < OO; ++oo) { float t = ss[c*OO + oo]; norm += t*t; }
    float scale = norm / ((1.f + norm) * sqrtf(norm + 1e-8f));
    float val = scale * s;
    g_v[b*CC*OO + tid] = val;
    if (dout) dout[b*CC*OO + tid] = val;
}

// ---------------- launcher ----------------
extern "C" void kernel_launch(void* const* d_in, const int* in_sizes, int n_in,
                              void* d_out, int out_size)
{
    const float* x  = (const float*)d_in[0];   // [32,3,64,64]
    const float* w1 = (const float*)d_in[1];   // [256,3,9,9]
    const float* b1 = (const float*)d_in[2];   // [256]
    const float* w2 = (const float*)d_in[3];   // [256,256,9,9]
    const float* b2 = (const float*)d_in[4];   // [256]
    const float* rw = (const float*)d_in[5];   // [32,10,8,16]
    float* out = (float*)d_out;

    static int smem_set = 0;
    if (!smem_set) {
        cudaFuncSetAttribute(conv_mma<1>,
                             cudaFuncAttributeMaxDynamicSharedMemorySize, CONV_SMEM);
        cudaFuncSetAttribute(conv_mma<2>,
                             cudaFuncAttributeMaxDynamicSharedMemorySize, CONV_SMEM);
        smem_set = 1;
    }

    // input + weight prep
    xpack_kernel<<<(NB*3*64*64 + 255)/256, 256>>>(x);
    w1split_kernel<<<(256*128 + 255)/256, 256>>>(w1);
    w2split_kernel<<<K2/2, 256>>>(w2);

    // conv1 -> g_h1p (mma.sync, relu+bias+pack fused)
    conv_mma<1><<<dim3(N1/128, 2), 256, CONV_SMEM>>>(b1);
    // conv2 -> g_caps (mma.sync)
    conv_mma<2><<<dim3(N2/128, 2), 256, CONV_SMEM>>>(b2);
    // squash primary caps
    squash_caps_kernel<<<(NB*RR*P2 + 255)/256, 256>>>();

    // routing iteration 1
    pass_kernel<1><<<dim3(NB, RR), 64>>>();
    sv_kernel<<<NB, CC*OO>>>(rw, nullptr);
    // routing iteration 2
    wv_kernel<<<(NB*RR*CC*DD + 127)/128, 128>>>(rw);
    pass_kernel<2><<<dim3(NB, RR), 64>>>();
    sv_kernel<<<NB, CC*OO>>>(rw, nullptr);
    // routing iteration 3 (final)
    wv_kernel<<<(NB*RR*CC*DD + 127)/128, 128>>>(rw);
    pass_kernel<3><<<dim3(NB, RR), 64>>>();
    sv_kernel<<<NB, CC*OO>>>(rw, out);
    (void)out_size;
}